// round 1
// baseline (speedup 1.0000x reference)
#include <cuda_runtime.h>
#include <math.h>

#define NN 131072
#define EE 2097152
#define DD 64
#define LL 3
#define RR 3
#define NBASE 2
#define BB 4096
#define KCOLS 256   // 64 self + 3*64 relations

// ---------------- device scratch (no allocs allowed) ----------------
__device__ float g_Wpack[6 * DD * KCOLS];   // [conv][k][col]  col<64: self, else relation r
__device__ float g_Bpack[6 * DD];
__device__ float g_T[(size_t)NN * 192];     // per-relation transformed features
__device__ float g_AGG[(size_t)NN * DD];    // aggregation target (init = h@Wself + b)
__device__ float g_Hl[(size_t)NN * DD];     // local-conv output
__device__ float g_Hg0[(size_t)NN * DD];    // global-conv outputs per layer (kept for MLP concat)
__device__ float g_Hg1[(size_t)NN * DD];
__device__ float g_Hg2[(size_t)NN * DD];

// ---------------- weight prep: W_r = sum_b C[r,b] V[b]; pack [6][64][256] ----------------
__global__ void prep_weights(const float* __restrict__ lV, const float* __restrict__ lC,
                             const float* __restrict__ lW, const float* __restrict__ lB,
                             const float* __restrict__ gV, const float* __restrict__ gC,
                             const float* __restrict__ gW, const float* __restrict__ gB) {
    int idx = blockIdx.x * blockDim.x + threadIdx.x;   // over 6*64*256
    if (idx >= 6 * DD * KCOLS) return;
    int c   = idx / (DD * KCOLS);
    int rem = idx % (DD * KCOLS);
    int k   = rem / KCOLS;
    int col = rem % KCOLS;
    int layer = c >> 1;
    bool local = ((c & 1) == 0);
    const float* V = local ? lV : gV;
    const float* C = local ? lC : gC;
    const float* W = local ? lW : gW;
    const float* B = local ? lB : gB;

    float val;
    if (col < DD) {
        // self-loop weight
        val = W[(size_t)layer * DD * DD + k * DD + col];
        if (k == 0) g_Bpack[c * DD + col] = B[layer * DD + col];
    } else {
        int r = (col - DD) / DD;
        int o = (col - DD) % DD;
        float s = 0.f;
        #pragma unroll
        for (int b = 0; b < NBASE; b++) {
            float cf = C[layer * RR * NBASE + r * NBASE + b];
            float vv = V[(size_t)layer * NBASE * DD * DD + (size_t)b * DD * DD + k * DD + o];
            s += cf * vv;
        }
        val = s;
    }
    g_Wpack[(size_t)c * DD * KCOLS + k * KCOLS + col] = val;
}

// ---------------- GEMM: [N,64] @ [64,256] -> T[N,192], AGG[N,64]=h@Wself+b ----------------
// block = 256 threads (tx 16 x ty 16); tile 128 rows x 128 cols; 8x8 per thread
__global__ __launch_bounds__(256, 2)
void gemm_kernel(const float* __restrict__ A, int conv) {
    __shared__ float hs[128][DD];      // 32KB
    __shared__ float ws[DD][128];      // 32KB

    const float* Wp = g_Wpack + (size_t)conv * DD * KCOLS;
    int tid = threadIdx.x;
    int tx = tid & 15, ty = tid >> 4;
    int row0 = blockIdx.x * 128;
    int col0 = blockIdx.y * 128;

    // load A tile: 128x64 floats = 2048 float4
    {
        const float4* Ag = (const float4*)(A + (size_t)row0 * DD);
        float4* hs4 = (float4*)&hs[0][0];
        #pragma unroll
        for (int t = 0; t < 8; t++) {
            int f = tid + t * 256;      // row = f/16, k4 = f%16
            hs4[f] = Ag[f];
        }
    }
    // load W tile: 64x128 = 2048 float4 (from a row of 256)
    {
        #pragma unroll
        for (int t = 0; t < 8; t++) {
            int f = tid + t * 256;
            int k = f >> 5;             // f / 32
            int c4 = f & 31;
            float4 w = *(const float4*)(Wp + k * KCOLS + col0 + c4 * 4);
            *(float4*)&ws[k][c4 * 4] = w;
        }
    }
    __syncthreads();

    float acc[8][8];
    #pragma unroll
    for (int i = 0; i < 8; i++)
        #pragma unroll
        for (int j = 0; j < 8; j++) acc[i][j] = 0.f;

    #pragma unroll 4
    for (int k = 0; k < DD; k++) {
        float a[8], b[8];
        #pragma unroll
        for (int i = 0; i < 8; i++) a[i] = hs[ty + 16 * i][k];
        #pragma unroll
        for (int j = 0; j < 8; j++) b[j] = ws[k][tx + 16 * j];
        #pragma unroll
        for (int i = 0; i < 8; i++)
            #pragma unroll
            for (int j = 0; j < 8; j++) acc[i][j] += a[i] * b[j];
    }

    #pragma unroll
    for (int j = 0; j < 8; j++) {
        int col = col0 + tx + 16 * j;
        #pragma unroll
        for (int i = 0; i < 8; i++) {
            int row = row0 + ty + 16 * i;
            float v = acc[i][j];
            if (col < DD) {
                g_AGG[(size_t)row * DD + col] = v + g_Bpack[conv * DD + col];
            } else {
                g_T[(size_t)row * 192 + (col - DD)] = v;
            }
        }
    }
}

// ---------------- scatter: AGG[dst] += norm * T[src, etype] ----------------
// 16 lanes per edge, float4 gather + 4 atomicAdds
__global__ void scatter_kernel(const int* __restrict__ src, const int* __restrict__ dst,
                               const int* __restrict__ etype, const float* __restrict__ norm) {
    long long t = (long long)blockIdx.x * blockDim.x + threadIdx.x;
    int edge = (int)(t >> 4);
    int lane = (int)(t & 15);
    if (edge >= EE) return;
    int s = src[edge];
    int d = dst[edge];
    int r = etype[edge];
    float w = norm[edge];
    float4 v = *(const float4*)(g_T + (size_t)s * 192 + r * DD + lane * 4);
    float* o = g_AGG + (size_t)d * DD + lane * 4;
    atomicAdd(o + 0, w * v.x);
    atomicAdd(o + 1, w * v.y);
    atomicAdd(o + 2, w * v.z);
    atomicAdd(o + 3, w * v.w);
}

// ---------------- activations ----------------
__global__ void act_elu_kernel(float* __restrict__ out) {
    int i = blockIdx.x * blockDim.x + threadIdx.x;   // over N*DD/4
    float4 v = ((const float4*)g_AGG)[i];
    v.x = v.x > 0.f ? v.x : (expf(v.x) - 1.f);
    v.y = v.y > 0.f ? v.y : (expf(v.y) - 1.f);
    v.z = v.z > 0.f ? v.z : (expf(v.z) - 1.f);
    v.w = v.w > 0.f ? v.w : (expf(v.w) - 1.f);
    ((float4*)out)[i] = v;
}

__global__ void act_leaky_kernel(float* __restrict__ out) {
    int i = blockIdx.x * blockDim.x + threadIdx.x;
    float4 v = ((const float4*)g_AGG)[i];
    v.x = v.x >= 0.f ? v.x : 0.01f * v.x;
    v.y = v.y >= 0.f ? v.y : 0.01f * v.y;
    v.z = v.z >= 0.f ? v.z : 0.01f * v.z;
    v.w = v.w >= 0.f ? v.w : 0.01f * v.w;
    ((float4*)out)[i] = v;
}

// ---------------- MLP head: [B,192] -> relu(128) -> sigmoid(1) ----------------
__global__ void mlp_kernel(const float* __restrict__ w1, const float* __restrict__ b1,
                           const float* __restrict__ w2, const float* __restrict__ b2,
                           float* __restrict__ out) {
    __shared__ float sub[192];
    __shared__ float red[128];
    int n = blockIdx.x;
    int tid = threadIdx.x;   // 128 threads
    // concat [Hg0 | Hg1 | Hg2] row n
    if (tid < 64) {
        sub[tid]       = g_Hg0[(size_t)n * DD + tid];
        sub[64 + tid]  = g_Hg1[(size_t)n * DD + tid];
        sub[128 + tid] = g_Hg2[(size_t)n * DD + tid];
    }
    __syncthreads();
    float acc = b1[tid];
    const float* w1r = w1 + tid * 192;
    #pragma unroll 8
    for (int k = 0; k < 192; k++) acc += sub[k] * w1r[k];
    red[tid] = fmaxf(acc, 0.f) * w2[tid];
    __syncthreads();
    #pragma unroll
    for (int s = 64; s > 0; s >>= 1) {
        if (tid < s) red[tid] += red[tid + s];
        __syncthreads();
    }
    if (tid == 0) {
        float z = red[0] + b2[0];
        out[n] = 1.f / (1.f + expf(-z));
    }
}

// ---------------- launch ----------------
extern "C" void kernel_launch(void* const* d_in, const int* in_sizes, int n_in,
                              void* d_out, int out_size) {
    const float* x     = (const float*)d_in[0];
    const int*   src   = (const int*)d_in[1];
    const int*   dst   = (const int*)d_in[2];
    const int*   etype = (const int*)d_in[3];
    const float* mask  = (const float*)d_in[4];
    const float* mask2 = (const float*)d_in[5];
    const float* lV = (const float*)d_in[6];
    const float* lC = (const float*)d_in[7];
    const float* lW = (const float*)d_in[8];
    const float* lB = (const float*)d_in[9];
    const float* gV = (const float*)d_in[10];
    const float* gC = (const float*)d_in[11];
    const float* gW = (const float*)d_in[12];
    const float* gB = (const float*)d_in[13];
    const float* w1 = (const float*)d_in[14];
    const float* b1 = (const float*)d_in[15];
    const float* w2 = (const float*)d_in[16];
    const float* b2 = (const float*)d_in[17];
    float* out = (float*)d_out;

    // resolve device-global scratch addresses for passing as kernel args
    float *Hl, *Hg0, *Hg1, *Hg2;
    cudaGetSymbolAddress((void**)&Hl,  g_Hl);
    cudaGetSymbolAddress((void**)&Hg0, g_Hg0);
    cudaGetSymbolAddress((void**)&Hg1, g_Hg1);
    cudaGetSymbolAddress((void**)&Hg2, g_Hg2);

    prep_weights<<<(6 * DD * KCOLS + 255) / 256, 256>>>(lV, lC, lW, lB, gV, gC, gW, gB);

    dim3 ggrid(NN / 128, 2);
    const int scat_blocks = (int)(((long long)EE * 16 + 255) / 256);
    const int act_blocks  = (NN * DD / 4) / 256;

    float* hg[3] = {Hg0, Hg1, Hg2};
    const float* h_in = x;
    for (int layer = 0; layer < LL; layer++) {
        // local conv (conv index 2*layer), norm = mask, ELU
        gemm_kernel<<<ggrid, 256>>>(h_in, 2 * layer);
        scatter_kernel<<<scat_blocks, 256>>>(src, dst, etype, mask);
        act_elu_kernel<<<act_blocks, 256>>>(Hl);
        // global conv (conv index 2*layer+1), norm = mask2, leaky relu
        gemm_kernel<<<ggrid, 256>>>(Hl, 2 * layer + 1);
        scatter_kernel<<<scat_blocks, 256>>>(src, dst, etype, mask2);
        act_leaky_kernel<<<act_blocks, 256>>>(hg[layer]);
        h_in = hg[layer];
    }

    mlp_kernel<<<BB, 128>>>(w1, b1, w2, b2, out);
}

// round 2
// speedup vs baseline: 1.6751x; 1.6751x over previous
#include <cuda_runtime.h>
#include <math.h>

#define NN 131072
#define EE 2097152
#define DD 64
#define LL 3
#define RR 3
#define NBASE 2
#define BB 4096
#define KCOLS 256   // 64 self + 3*64 relations

// ---------------- device scratch (no allocs allowed) ----------------
__device__ float g_Wpack[6 * DD * KCOLS];
__device__ float g_Bpack[6 * DD];
__device__ float g_T[(size_t)NN * 192];     // per-relation transformed features
__device__ float g_AGG[(size_t)NN * DD];    // self-loop + bias (gather adds edges on top)
__device__ float g_Hl[(size_t)NN * DD];
__device__ float g_Hg0[(size_t)NN * DD];
__device__ float g_Hg1[(size_t)NN * DD];
__device__ float g_Hg2[(size_t)NN * DD];
// CSR structures (built once per launch; graph is identical for all 6 convs)
__device__ int   g_cnt[NN];
__device__ int   g_cur[NN];
__device__ int   g_rowptr[NN + 1];
__device__ int   g_off[EE];    // src*192 + etype*64 (precombined gather offset)
__device__ float g_n1[EE];     // mask  in CSR order
__device__ float g_n2[EE];     // mask2 in CSR order

// ---------------- weight prep ----------------
__global__ void prep_weights(const float* __restrict__ lV, const float* __restrict__ lC,
                             const float* __restrict__ lW, const float* __restrict__ lB,
                             const float* __restrict__ gV, const float* __restrict__ gC,
                             const float* __restrict__ gW, const float* __restrict__ gB) {
    int idx = blockIdx.x * blockDim.x + threadIdx.x;
    if (idx >= 6 * DD * KCOLS) return;
    int c   = idx / (DD * KCOLS);
    int rem = idx % (DD * KCOLS);
    int k   = rem / KCOLS;
    int col = rem % KCOLS;
    int layer = c >> 1;
    bool local = ((c & 1) == 0);
    const float* V = local ? lV : gV;
    const float* C = local ? lC : gC;
    const float* W = local ? lW : gW;
    const float* B = local ? lB : gB;

    float val;
    if (col < DD) {
        val = W[(size_t)layer * DD * DD + k * DD + col];
        if (k == 0) g_Bpack[c * DD + col] = B[layer * DD + col];
    } else {
        int r = (col - DD) / DD;
        int o = (col - DD) % DD;
        float s = 0.f;
        #pragma unroll
        for (int b = 0; b < NBASE; b++) {
            float cf = C[layer * RR * NBASE + r * NBASE + b];
            float vv = V[(size_t)layer * NBASE * DD * DD + (size_t)b * DD * DD + k * DD + o];
            s += cf * vv;
        }
        val = s;
    }
    g_Wpack[(size_t)c * DD * KCOLS + k * KCOLS + col] = val;
}

// ---------------- CSR build ----------------
__global__ void zero_cnt_kernel() {
    int i = blockIdx.x * blockDim.x + threadIdx.x;
    if (i < NN) g_cnt[i] = 0;
}

__global__ void count_kernel(const int* __restrict__ dst) {
    int e = blockIdx.x * blockDim.x + threadIdx.x;
    if (e < EE) atomicAdd(&g_cnt[dst[e]], 1);
}

__global__ void scan_kernel() {   // single block, 1024 threads; 128 nodes per thread
    __shared__ int s[1024];
    int tid = threadIdx.x;
    int base = tid * 128;
    int sum = 0;
    #pragma unroll 4
    for (int i = 0; i < 128; i++) sum += g_cnt[base + i];
    s[tid] = sum;
    __syncthreads();
    // inclusive Hillis-Steele
    #pragma unroll
    for (int d = 1; d < 1024; d <<= 1) {
        int v = 0;
        if (tid >= d) v = s[tid - d];
        __syncthreads();
        s[tid] += v;
        __syncthreads();
    }
    int run = s[tid] - sum;   // exclusive prefix for this chunk
    for (int i = 0; i < 128; i++) {
        g_rowptr[base + i] = run;
        g_cur[base + i] = run;
        run += g_cnt[base + i];
    }
    if (tid == 1023) g_rowptr[NN] = run;
}

__global__ void fill_kernel(const int* __restrict__ src, const int* __restrict__ dst,
                            const int* __restrict__ etype,
                            const float* __restrict__ mask, const float* __restrict__ mask2) {
    int e = blockIdx.x * blockDim.x + threadIdx.x;
    if (e >= EE) return;
    int d = dst[e];
    int pos = atomicAdd(&g_cur[d], 1);
    g_off[pos] = src[e] * 192 + etype[e] * DD;
    g_n1[pos] = mask[e];
    g_n2[pos] = mask2[e];
}

// ---------------- GEMM: [N,64] @ [64,256] -> T[N,192], AGG[N,64]=h@Wself+b ----------------
// block 256 (16x16), tile 128x128, 8x8 per thread, vectorized smem
__global__ __launch_bounds__(256, 2)
void gemm_kernel(const float* __restrict__ A, int conv) {
    extern __shared__ float smem[];
    float* hsT = smem;              // [64][132] transposed A tile
    float* ws  = smem + 64 * 132;   // [64][128]

    const float* Wp = g_Wpack + (size_t)conv * DD * KCOLS;
    int tid = threadIdx.x;
    int row0 = blockIdx.x * 128;
    int col0 = blockIdx.y * 128;

    // A tile with 4x4 register transpose: work item f covers rows 4r..4r+3, k 4k4..4k4+3
    {
        const float* Ag = A + (size_t)row0 * DD;
        #pragma unroll
        for (int it = 0; it < 2; it++) {
            int f = tid + it * 256;           // 0..511
            int k4 = f & 15;
            int r4 = f >> 4;                  // 0..31
            float4 v0 = *(const float4*)(Ag + (size_t)(r4 * 4 + 0) * DD + k4 * 4);
            float4 v1 = *(const float4*)(Ag + (size_t)(r4 * 4 + 1) * DD + k4 * 4);
            float4 v2 = *(const float4*)(Ag + (size_t)(r4 * 4 + 2) * DD + k4 * 4);
            float4 v3 = *(const float4*)(Ag + (size_t)(r4 * 4 + 3) * DD + k4 * 4);
            *(float4*)(hsT + (k4 * 4 + 0) * 132 + r4 * 4) = make_float4(v0.x, v1.x, v2.x, v3.x);
            *(float4*)(hsT + (k4 * 4 + 1) * 132 + r4 * 4) = make_float4(v0.y, v1.y, v2.y, v3.y);
            *(float4*)(hsT + (k4 * 4 + 2) * 132 + r4 * 4) = make_float4(v0.z, v1.z, v2.z, v3.z);
            *(float4*)(hsT + (k4 * 4 + 3) * 132 + r4 * 4) = make_float4(v0.w, v1.w, v2.w, v3.w);
        }
    }
    // W tile
    #pragma unroll
    for (int t = 0; t < 8; t++) {
        int f = tid + t * 256;
        int k = f >> 5, c4 = f & 31;
        *(float4*)(ws + k * 128 + c4 * 4) = *(const float4*)(Wp + k * KCOLS + col0 + c4 * 4);
    }
    __syncthreads();

    int tx = tid & 15, ty = tid >> 4;
    float acc[8][8];
    #pragma unroll
    for (int i = 0; i < 8; i++)
        #pragma unroll
        for (int j = 0; j < 8; j++) acc[i][j] = 0.f;

    #pragma unroll 8
    for (int k = 0; k < DD; k++) {
        float4 a0 = *(const float4*)(hsT + k * 132 + ty * 8);
        float4 a1 = *(const float4*)(hsT + k * 132 + ty * 8 + 4);
        float4 b0 = *(const float4*)(ws + k * 128 + tx * 8);
        float4 b1 = *(const float4*)(ws + k * 128 + tx * 8 + 4);
        float a[8] = {a0.x, a0.y, a0.z, a0.w, a1.x, a1.y, a1.z, a1.w};
        float b[8] = {b0.x, b0.y, b0.z, b0.w, b1.x, b1.y, b1.z, b1.w};
        #pragma unroll
        for (int i = 0; i < 8; i++)
            #pragma unroll
            for (int j = 0; j < 8; j++) acc[i][j] += a[i] * b[j];
    }

    int colg = col0 + tx * 8;
    if (colg < DD) {
        float4 bb0 = *(const float4*)(g_Bpack + conv * DD + colg);
        float4 bb1 = *(const float4*)(g_Bpack + conv * DD + colg + 4);
        #pragma unroll
        for (int i = 0; i < 8; i++) {
            int row = row0 + ty * 8 + i;
            float4 o0 = make_float4(acc[i][0] + bb0.x, acc[i][1] + bb0.y,
                                    acc[i][2] + bb0.z, acc[i][3] + bb0.w);
            float4 o1 = make_float4(acc[i][4] + bb1.x, acc[i][5] + bb1.y,
                                    acc[i][6] + bb1.z, acc[i][7] + bb1.w);
            *(float4*)(g_AGG + (size_t)row * DD + colg)     = o0;
            *(float4*)(g_AGG + (size_t)row * DD + colg + 4) = o1;
        }
    } else {
        int ct = colg - DD;
        #pragma unroll
        for (int i = 0; i < 8; i++) {
            int row = row0 + ty * 8 + i;
            *(float4*)(g_T + (size_t)row * 192 + ct) =
                make_float4(acc[i][0], acc[i][1], acc[i][2], acc[i][3]);
            *(float4*)(g_T + (size_t)row * 192 + ct + 4) =
                make_float4(acc[i][4], acc[i][5], acc[i][6], acc[i][7]);
        }
    }
}

// ---------------- fused gather + self-loop + activation ----------------
// 16 threads per node (float4 lanes), ACT: 0 = ELU, 1 = leaky_relu(0.01)
template <int ACT>
__global__ void gather_kernel(const float* __restrict__ norm, float* __restrict__ Hout,
                              int nNodes) {
    int t = blockIdx.x * blockDim.x + threadIdx.x;
    int node = t >> 4;
    int lane = t & 15;
    if (node >= nNodes) return;
    int e0 = g_rowptr[node];
    int e1 = g_rowptr[node + 1];
    float4 acc = *(const float4*)(g_AGG + (size_t)node * DD + lane * 4);
    for (int e = e0; e < e1; e++) {
        int off = __ldg(&g_off[e]);
        float w = __ldg(&norm[e]);
        float4 v = *(const float4*)(g_T + (size_t)off + lane * 4);
        acc.x = fmaf(w, v.x, acc.x);
        acc.y = fmaf(w, v.y, acc.y);
        acc.z = fmaf(w, v.z, acc.z);
        acc.w = fmaf(w, v.w, acc.w);
    }
    if (ACT == 0) {
        acc.x = acc.x > 0.f ? acc.x : expm1f(acc.x);
        acc.y = acc.y > 0.f ? acc.y : expm1f(acc.y);
        acc.z = acc.z > 0.f ? acc.z : expm1f(acc.z);
        acc.w = acc.w > 0.f ? acc.w : expm1f(acc.w);
    } else {
        acc.x = acc.x >= 0.f ? acc.x : 0.01f * acc.x;
        acc.y = acc.y >= 0.f ? acc.y : 0.01f * acc.y;
        acc.z = acc.z >= 0.f ? acc.z : 0.01f * acc.z;
        acc.w = acc.w >= 0.f ? acc.w : 0.01f * acc.w;
    }
    *(float4*)(Hout + (size_t)node * DD + lane * 4) = acc;
}

// ---------------- MLP head ----------------
__global__ void mlp_kernel(const float* __restrict__ w1, const float* __restrict__ b1,
                           const float* __restrict__ w2, const float* __restrict__ b2,
                           float* __restrict__ out) {
    __shared__ float sub[192];
    __shared__ float red[128];
    int n = blockIdx.x;
    int tid = threadIdx.x;
    if (tid < 64) {
        sub[tid]       = g_Hg0[(size_t)n * DD + tid];
        sub[64 + tid]  = g_Hg1[(size_t)n * DD + tid];
        sub[128 + tid] = g_Hg2[(size_t)n * DD + tid];
    }
    __syncthreads();
    float acc = b1[tid];
    const float* w1r = w1 + tid * 192;
    #pragma unroll 8
    for (int k = 0; k < 192; k++) acc += sub[k] * w1r[k];
    red[tid] = fmaxf(acc, 0.f) * w2[tid];
    __syncthreads();
    #pragma unroll
    for (int s = 64; s > 0; s >>= 1) {
        if (tid < s) red[tid] += red[tid + s];
        __syncthreads();
    }
    if (tid == 0) {
        float z = red[0] + b2[0];
        out[n] = 1.f / (1.f + expf(-z));
    }
}

// ---------------- launch ----------------
extern "C" void kernel_launch(void* const* d_in, const int* in_sizes, int n_in,
                              void* d_out, int out_size) {
    const float* x     = (const float*)d_in[0];
    const int*   src   = (const int*)d_in[1];
    const int*   dst   = (const int*)d_in[2];
    const int*   etype = (const int*)d_in[3];
    const float* mask  = (const float*)d_in[4];
    const float* mask2 = (const float*)d_in[5];
    const float* lV = (const float*)d_in[6];
    const float* lC = (const float*)d_in[7];
    const float* lW = (const float*)d_in[8];
    const float* lB = (const float*)d_in[9];
    const float* gV = (const float*)d_in[10];
    const float* gC = (const float*)d_in[11];
    const float* gW = (const float*)d_in[12];
    const float* gB = (const float*)d_in[13];
    const float* w1 = (const float*)d_in[14];
    const float* b1 = (const float*)d_in[15];
    const float* w2 = (const float*)d_in[16];
    const float* b2 = (const float*)d_in[17];
    float* out = (float*)d_out;

    float *Hl, *Hg0, *Hg1, *Hg2, *n1p, *n2p;
    cudaGetSymbolAddress((void**)&Hl,  g_Hl);
    cudaGetSymbolAddress((void**)&Hg0, g_Hg0);
    cudaGetSymbolAddress((void**)&Hg1, g_Hg1);
    cudaGetSymbolAddress((void**)&Hg2, g_Hg2);
    cudaGetSymbolAddress((void**)&n1p, g_n1);
    cudaGetSymbolAddress((void**)&n2p, g_n2);

    const int GEMM_SMEM = (64 * 132 + 64 * 128) * 4;
    cudaFuncSetAttribute(gemm_kernel, cudaFuncAttributeMaxDynamicSharedMemorySize, GEMM_SMEM);

    // weights + CSR (graph identical across all 6 convs)
    prep_weights<<<(6 * DD * KCOLS + 255) / 256, 256>>>(lV, lC, lW, lB, gV, gC, gW, gB);
    zero_cnt_kernel<<<NN / 256, 256>>>();
    count_kernel<<<EE / 256, 256>>>(dst);
    scan_kernel<<<1, 1024>>>();
    fill_kernel<<<EE / 256, 256>>>(src, dst, etype, mask, mask2);

    dim3 ggrid(NN / 128, 2);
    float* hg[3] = {Hg0, Hg1, Hg2};
    const float* h_in = x;
    for (int layer = 0; layer < LL; layer++) {
        // local conv: norm = mask (g_n1), ELU
        gemm_kernel<<<ggrid, 256, GEMM_SMEM>>>(h_in, 2 * layer);
        gather_kernel<0><<<(NN * 16) / 256, 256>>>(n1p, Hl, NN);
        // global conv: norm = mask2 (g_n2), leaky relu; last layer only needs BB nodes
        gemm_kernel<<<ggrid, 256, GEMM_SMEM>>>(Hl, 2 * layer + 1);
        int nOut = (layer == LL - 1) ? BB : NN;
        gather_kernel<1><<<(nOut * 16 + 255) / 256, 256>>>(n2p, hg[layer], nOut);
        h_in = hg[layer];
    }

    mlp_kernel<<<BB, 128>>>(w1, b1, w2, b2, out);
}

// round 3
// speedup vs baseline: 2.3147x; 1.3818x over previous
#include <cuda_runtime.h>
#include <math.h>

#define NN 131072
#define EE 2097152
#define DD 64
#define LL 3
#define RR 3
#define NBASE 2
#define BB 4096
#define KCOLS 256   // 64 self + 3*64 relations

// ---------------- device scratch (no allocs allowed) ----------------
__device__ float g_Wpack[6 * DD * KCOLS];
__device__ float g_Bpack[6 * DD];
__device__ float g_T[(size_t)NN * 192];     // per-relation transformed features
__device__ float g_AGG[(size_t)NN * DD];    // self-loop + bias (gather adds edges on top)
__device__ float g_Hl[(size_t)NN * DD];
__device__ float g_Hg0[(size_t)NN * DD];
__device__ float g_Hg1[(size_t)NN * DD];
__device__ float g_Hg2[(size_t)NN * DD];
// CSR structures (built once per launch; graph is identical for all 6 convs)
__device__ int   g_cnt[NN];
__device__ int   g_cur[NN];
__device__ int   g_rowptr[NN + 1];
__device__ int   g_off[EE];    // src*192 + etype*64 (precombined gather offset)
__device__ float g_n1[EE];     // mask  in CSR order
__device__ float g_n2[EE];     // mask2 in CSR order
__device__ int   g_blksum[512];
__device__ int   g_blkpre[512];

// ---------------- weight prep ----------------
__global__ void prep_weights(const float* __restrict__ lV, const float* __restrict__ lC,
                             const float* __restrict__ lW, const float* __restrict__ lB,
                             const float* __restrict__ gV, const float* __restrict__ gC,
                             const float* __restrict__ gW, const float* __restrict__ gB) {
    int idx = blockIdx.x * blockDim.x + threadIdx.x;
    if (idx >= 6 * DD * KCOLS) return;
    int c   = idx / (DD * KCOLS);
    int rem = idx % (DD * KCOLS);
    int k   = rem / KCOLS;
    int col = rem % KCOLS;
    int layer = c >> 1;
    bool local = ((c & 1) == 0);
    const float* V = local ? lV : gV;
    const float* C = local ? lC : gC;
    const float* W = local ? lW : gW;
    const float* B = local ? lB : gB;

    float val;
    if (col < DD) {
        val = W[(size_t)layer * DD * DD + k * DD + col];
        if (k == 0) g_Bpack[c * DD + col] = B[layer * DD + col];
    } else {
        int r = (col - DD) / DD;
        int o = (col - DD) % DD;
        float s = 0.f;
        #pragma unroll
        for (int b = 0; b < NBASE; b++) {
            float cf = C[layer * RR * NBASE + r * NBASE + b];
            float vv = V[(size_t)layer * NBASE * DD * DD + (size_t)b * DD * DD + k * DD + o];
            s += cf * vv;
        }
        val = s;
    }
    g_Wpack[(size_t)c * DD * KCOLS + k * KCOLS + col] = val;
}

// ---------------- CSR build (parallel scan) ----------------
__global__ void zero_cnt_kernel() {
    int i = blockIdx.x * blockDim.x + threadIdx.x;
    if (i < NN) g_cnt[i] = 0;
}

__global__ void count_kernel(const int* __restrict__ dst) {
    int e = blockIdx.x * blockDim.x + threadIdx.x;
    if (e < EE) atomicAdd(&g_cnt[dst[e]], 1);
}

// 512 blocks x 256 threads: per-block sum of 256 counts
__global__ void partial_sum_kernel() {
    __shared__ int s[256];
    int tid = threadIdx.x;
    s[tid] = g_cnt[blockIdx.x * 256 + tid];
    __syncthreads();
    #pragma unroll
    for (int d = 128; d > 0; d >>= 1) {
        if (tid < d) s[tid] += s[tid + d];
        __syncthreads();
    }
    if (tid == 0) g_blksum[blockIdx.x] = s[0];
}

// single block 512: exclusive prefix of 512 block sums
__global__ void scan512_kernel() {
    __shared__ int s[512];
    int tid = threadIdx.x;
    int v = g_blksum[tid];
    s[tid] = v;
    __syncthreads();
    #pragma unroll
    for (int d = 1; d < 512; d <<= 1) {
        int t = (tid >= d) ? s[tid - d] : 0;
        __syncthreads();
        s[tid] += t;
        __syncthreads();
    }
    g_blkpre[tid] = s[tid] - v;   // exclusive
}

// 512 blocks x 256: within-block exclusive scan + base -> rowptr / cur
__global__ void writeptr_kernel() {
    __shared__ int s[256];
    int tid = threadIdx.x;
    int i = blockIdx.x * 256 + tid;
    int v = g_cnt[i];
    s[tid] = v;
    __syncthreads();
    #pragma unroll
    for (int d = 1; d < 256; d <<= 1) {
        int t = (tid >= d) ? s[tid - d] : 0;
        __syncthreads();
        s[tid] += t;
        __syncthreads();
    }
    int pos = g_blkpre[blockIdx.x] + s[tid] - v;   // exclusive prefix
    g_rowptr[i] = pos;
    g_cur[i] = pos;
    if (i == NN - 1) g_rowptr[NN] = EE;
}

__global__ void fill_kernel(const int* __restrict__ src, const int* __restrict__ dst,
                            const int* __restrict__ etype,
                            const float* __restrict__ mask, const float* __restrict__ mask2) {
    int e = blockIdx.x * blockDim.x + threadIdx.x;
    if (e >= EE) return;
    int d = dst[e];
    int pos = atomicAdd(&g_cur[d], 1);
    g_off[pos] = src[e] * 192 + etype[e] * DD;
    g_n1[pos] = mask[e];
    g_n2[pos] = mask2[e];
}

// ---------------- TF32 tensor-core GEMM (3xTF32 for fp32-grade accuracy) ----------------
// C[N,256] = A[N,64] @ W[64,256]; block tile 128x128 (grid.y=2), 8 warps (4m x 2n),
// warp tile 32x64 -> 2 m-tiles x 8 n-tiles of m16n8k8.
__device__ __forceinline__ unsigned f2tf32(float x) {
    unsigned r;
    asm("cvt.rna.tf32.f32 %0, %1;" : "=r"(r) : "f"(x));
    return r;
}

__device__ __forceinline__ void mma_tf32(float* c, const unsigned* a, const unsigned* b) {
    asm volatile(
        "mma.sync.aligned.m16n8k8.row.col.f32.tf32.tf32.f32 "
        "{%0,%1,%2,%3}, {%4,%5,%6,%7}, {%8,%9}, {%0,%1,%2,%3};"
        : "+f"(c[0]), "+f"(c[1]), "+f"(c[2]), "+f"(c[3])
        : "r"(a[0]), "r"(a[1]), "r"(a[2]), "r"(a[3]), "r"(b[0]), "r"(b[1]));
}

#define AS_STRIDE 68
#define WS_STRIDE 136

__global__ __launch_bounds__(256, 2)
void gemm_tc_kernel(const float* __restrict__ A, int conv) {
    extern __shared__ float smem[];
    float* As = smem;                       // [128][68]
    float* Ws = smem + 128 * AS_STRIDE;     // [64][136]

    const float* Wp = g_Wpack + (size_t)conv * DD * KCOLS;
    int tid = threadIdx.x;
    int row0 = blockIdx.x * 128;
    int col0 = blockIdx.y * 128;

    // load A tile 128x64 (float4)
    {
        const float4* Ag = (const float4*)(A + (size_t)row0 * DD);
        #pragma unroll
        for (int it = 0; it < 8; it++) {
            int f = tid + it * 256;         // 0..2047
            int row = f >> 4, k4 = f & 15;
            *(float4*)(As + row * AS_STRIDE + k4 * 4) = Ag[f];
        }
    }
    // load W tile 64x128
    {
        #pragma unroll
        for (int it = 0; it < 8; it++) {
            int f = tid + it * 256;
            int k = f >> 5, c4 = f & 31;
            *(float4*)(Ws + k * WS_STRIDE + c4 * 4) =
                *(const float4*)(Wp + k * KCOLS + col0 + c4 * 4);
        }
    }
    __syncthreads();

    int warp = tid >> 5;
    int lane = tid & 31;
    int warp_m = warp & 3;      // 0..3 -> rows warp_m*32
    int warp_n = warp >> 2;     // 0..1 -> cols warp_n*64
    int group = lane >> 2;      // 0..7
    int q     = lane & 3;       // 0..3

    float acc[2][8][4];
    #pragma unroll
    for (int mi = 0; mi < 2; mi++)
        #pragma unroll
        for (int ni = 0; ni < 8; ni++)
            #pragma unroll
            for (int t = 0; t < 4; t++) acc[mi][ni][t] = 0.f;

    #pragma unroll
    for (int ks = 0; ks < 8; ks++) {
        int k0 = ks * 8;
        unsigned abig[2][4], ares[2][4];
        #pragma unroll
        for (int mi = 0; mi < 2; mi++) {
            int rb = warp_m * 32 + mi * 16 + group;
            float a0 = As[rb * AS_STRIDE + k0 + q];
            float a1 = As[(rb + 8) * AS_STRIDE + k0 + q];
            float a2 = As[rb * AS_STRIDE + k0 + q + 4];
            float a3 = As[(rb + 8) * AS_STRIDE + k0 + q + 4];
            abig[mi][0] = f2tf32(a0); ares[mi][0] = f2tf32(a0 - __uint_as_float(abig[mi][0]));
            abig[mi][1] = f2tf32(a1); ares[mi][1] = f2tf32(a1 - __uint_as_float(abig[mi][1]));
            abig[mi][2] = f2tf32(a2); ares[mi][2] = f2tf32(a2 - __uint_as_float(abig[mi][2]));
            abig[mi][3] = f2tf32(a3); ares[mi][3] = f2tf32(a3 - __uint_as_float(abig[mi][3]));
        }
        #pragma unroll
        for (int ni = 0; ni < 8; ni++) {
            int cn = warp_n * 64 + ni * 8 + group;
            float b0f = Ws[(k0 + q) * WS_STRIDE + cn];
            float b1f = Ws[(k0 + q + 4) * WS_STRIDE + cn];
            unsigned bbig[2], bres[2];
            bbig[0] = f2tf32(b0f); bres[0] = f2tf32(b0f - __uint_as_float(bbig[0]));
            bbig[1] = f2tf32(b1f); bres[1] = f2tf32(b1f - __uint_as_float(bbig[1]));
            #pragma unroll
            for (int mi = 0; mi < 2; mi++) {
                mma_tf32(acc[mi][ni], ares[mi], bbig);   // residual terms first
                mma_tf32(acc[mi][ni], abig[mi], bres);
                mma_tf32(acc[mi][ni], abig[mi], bbig);
            }
        }
    }

    // epilogue: cols < 64 -> AGG (+bias), else -> T
    #pragma unroll
    for (int ni = 0; ni < 8; ni++) {
        int cg = col0 + warp_n * 64 + ni * 8 + 2 * q;
        #pragma unroll
        for (int mi = 0; mi < 2; mi++) {
            int r0 = row0 + warp_m * 32 + mi * 16 + group;
            float* a4 = acc[mi][ni];
            if (cg < DD) {
                float bv0 = g_Bpack[conv * DD + cg];
                float bv1 = g_Bpack[conv * DD + cg + 1];
                *(float2*)(g_AGG + (size_t)r0 * DD + cg)       = make_float2(a4[0] + bv0, a4[1] + bv1);
                *(float2*)(g_AGG + (size_t)(r0 + 8) * DD + cg) = make_float2(a4[2] + bv0, a4[3] + bv1);
            } else {
                int ct = cg - DD;
                *(float2*)(g_T + (size_t)r0 * 192 + ct)       = make_float2(a4[0], a4[1]);
                *(float2*)(g_T + (size_t)(r0 + 8) * 192 + ct) = make_float2(a4[2], a4[3]);
            }
        }
    }
}

// ---------------- fused gather + self-loop + activation ----------------
template <int ACT>
__global__ void gather_kernel(const float* __restrict__ norm, float* __restrict__ Hout,
                              int nNodes) {
    int t = blockIdx.x * blockDim.x + threadIdx.x;
    int node = t >> 4;
    int lane = t & 15;
    if (node >= nNodes) return;
    int e0 = g_rowptr[node];
    int e1 = g_rowptr[node + 1];
    float4 acc = *(const float4*)(g_AGG + (size_t)node * DD + lane * 4);
    for (int e = e0; e < e1; e++) {
        int off = __ldg(&g_off[e]);
        float w = __ldg(&norm[e]);
        float4 v = *(const float4*)(g_T + (size_t)off + lane * 4);
        acc.x = fmaf(w, v.x, acc.x);
        acc.y = fmaf(w, v.y, acc.y);
        acc.z = fmaf(w, v.z, acc.z);
        acc.w = fmaf(w, v.w, acc.w);
    }
    if (ACT == 0) {
        acc.x = acc.x > 0.f ? acc.x : expm1f(acc.x);
        acc.y = acc.y > 0.f ? acc.y : expm1f(acc.y);
        acc.z = acc.z > 0.f ? acc.z : expm1f(acc.z);
        acc.w = acc.w > 0.f ? acc.w : expm1f(acc.w);
    } else {
        acc.x = acc.x >= 0.f ? acc.x : 0.01f * acc.x;
        acc.y = acc.y >= 0.f ? acc.y : 0.01f * acc.y;
        acc.z = acc.z >= 0.f ? acc.z : 0.01f * acc.z;
        acc.w = acc.w >= 0.f ? acc.w : 0.01f * acc.w;
    }
    *(float4*)(Hout + (size_t)node * DD + lane * 4) = acc;
}

// ---------------- MLP head ----------------
__global__ void mlp_kernel(const float* __restrict__ w1, const float* __restrict__ b1,
                           const float* __restrict__ w2, const float* __restrict__ b2,
                           float* __restrict__ out) {
    __shared__ float sub[192];
    __shared__ float red[128];
    int n = blockIdx.x;
    int tid = threadIdx.x;
    if (tid < 64) {
        sub[tid]       = g_Hg0[(size_t)n * DD + tid];
        sub[64 + tid]  = g_Hg1[(size_t)n * DD + tid];
        sub[128 + tid] = g_Hg2[(size_t)n * DD + tid];
    }
    __syncthreads();
    float acc = b1[tid];
    const float* w1r = w1 + tid * 192;
    #pragma unroll 8
    for (int k = 0; k < 192; k++) acc += sub[k] * w1r[k];
    red[tid] = fmaxf(acc, 0.f) * w2[tid];
    __syncthreads();
    #pragma unroll
    for (int s = 64; s > 0; s >>= 1) {
        if (tid < s) red[tid] += red[tid + s];
        __syncthreads();
    }
    if (tid == 0) {
        float z = red[0] + b2[0];
        out[n] = 1.f / (1.f + expf(-z));
    }
}

// ---------------- launch ----------------
extern "C" void kernel_launch(void* const* d_in, const int* in_sizes, int n_in,
                              void* d_out, int out_size) {
    const float* x     = (const float*)d_in[0];
    const int*   src   = (const int*)d_in[1];
    const int*   dst   = (const int*)d_in[2];
    const int*   etype = (const int*)d_in[3];
    const float* mask  = (const float*)d_in[4];
    const float* mask2 = (const float*)d_in[5];
    const float* lV = (const float*)d_in[6];
    const float* lC = (const float*)d_in[7];
    const float* lW = (const float*)d_in[8];
    const float* lB = (const float*)d_in[9];
    const float* gV = (const float*)d_in[10];
    const float* gC = (const float*)d_in[11];
    const float* gW = (const float*)d_in[12];
    const float* gB = (const float*)d_in[13];
    const float* w1 = (const float*)d_in[14];
    const float* b1 = (const float*)d_in[15];
    const float* w2 = (const float*)d_in[16];
    const float* b2 = (const float*)d_in[17];
    float* out = (float*)d_out;

    float *Hl, *Hg0, *Hg1, *Hg2, *n1p, *n2p;
    cudaGetSymbolAddress((void**)&Hl,  g_Hl);
    cudaGetSymbolAddress((void**)&Hg0, g_Hg0);
    cudaGetSymbolAddress((void**)&Hg1, g_Hg1);
    cudaGetSymbolAddress((void**)&Hg2, g_Hg2);
    cudaGetSymbolAddress((void**)&n1p, g_n1);
    cudaGetSymbolAddress((void**)&n2p, g_n2);

    const int GEMM_SMEM = (128 * AS_STRIDE + 64 * WS_STRIDE) * 4;
    cudaFuncSetAttribute(gemm_tc_kernel, cudaFuncAttributeMaxDynamicSharedMemorySize, GEMM_SMEM);

    // weights + CSR (graph identical across all 6 convs)
    prep_weights<<<(6 * DD * KCOLS + 255) / 256, 256>>>(lV, lC, lW, lB, gV, gC, gW, gB);
    zero_cnt_kernel<<<NN / 256, 256>>>();
    count_kernel<<<EE / 256, 256>>>(dst);
    partial_sum_kernel<<<512, 256>>>();
    scan512_kernel<<<1, 512>>>();
    writeptr_kernel<<<512, 256>>>();
    fill_kernel<<<EE / 256, 256>>>(src, dst, etype, mask, mask2);

    dim3 ggrid(NN / 128, 2);
    float* hg[3] = {Hg0, Hg1, Hg2};
    const float* h_in = x;
    for (int layer = 0; layer < LL; layer++) {
        // local conv: norm = mask (g_n1), ELU
        gemm_tc_kernel<<<ggrid, 256, GEMM_SMEM>>>(h_in, 2 * layer);
        gather_kernel<0><<<(NN * 16) / 256, 256>>>(n1p, Hl, NN);
        // global conv: norm = mask2 (g_n2), leaky relu; last layer only needs BB nodes
        gemm_tc_kernel<<<ggrid, 256, GEMM_SMEM>>>(Hl, 2 * layer + 1);
        int nOut = (layer == LL - 1) ? BB : NN;
        gather_kernel<1><<<(nOut * 16 + 255) / 256, 256>>>(n2p, hg[layer], nOut);
        h_in = hg[layer];
    }

    mlp_kernel<<<BB, 128>>>(w1, b1, w2, b2, out);
}

// round 4
// speedup vs baseline: 2.4911x; 1.0762x over previous
#include <cuda_runtime.h>
#include <math.h>

#define NN 131072
#define EE 2097152
#define DD 64
#define LL 3
#define RR 3
#define NBASE 2
#define BB 4096

// ---------------- device scratch (no allocs allowed) ----------------
__device__ float g_Wk[6 * 192 * DD];        // stacked [V_b0 | V_b1 | Wself] per conv
__device__ float g_Bpack[6 * DD];
__device__ float g_AGGB[(size_t)NN * 128];  // 2 basis accumulators per node
__device__ float g_Hl[(size_t)NN * DD];
__device__ float g_Hg0[(size_t)NN * DD];
__device__ float g_Hg1[(size_t)NN * DD];
__device__ float g_Hg2[(size_t)NN * DD];
// CSR structures (built once; graph identical for all 6 convs)
__device__ int   g_cnt[NN];
__device__ int   g_cur[NN];
__device__ int   g_rowptr[NN + 1];
__device__ int   g_se[EE];     // src*64 + etype (etype < 64)
__device__ float g_n1[EE];     // mask  in CSR order
__device__ float g_n2[EE];     // mask2 in CSR order
__device__ int   g_blksum[512];
__device__ int   g_blkpre[512];

// ---------------- weight prep: g_Wk[conv][row<128: V[b=row/64][row%64][col]; else Wself] ----
__global__ void prep_weights(const float* __restrict__ lV, const float* __restrict__ lW,
                             const float* __restrict__ lB,
                             const float* __restrict__ gV, const float* __restrict__ gW,
                             const float* __restrict__ gB) {
    int idx = blockIdx.x * blockDim.x + threadIdx.x;   // over 6*192*64
    if (idx >= 6 * 192 * DD) return;
    int c   = idx / (192 * DD);
    int rem = idx % (192 * DD);
    int row = rem / DD;
    int col = rem % DD;
    int layer = c >> 1;
    bool local = ((c & 1) == 0);
    const float* V = local ? lV : gV;
    const float* W = local ? lW : gW;
    const float* B = local ? lB : gB;

    float val;
    if (row < 128) {
        int b = row >> 6, d = row & 63;
        val = V[(((size_t)layer * NBASE + b) * DD + d) * DD + col];
    } else {
        int d = row - 128;
        val = W[((size_t)layer * DD + d) * DD + col];
    }
    g_Wk[idx] = val;
    if (row == 0) g_Bpack[c * DD + col] = B[layer * DD + col];
}

// ---------------- CSR build (parallel scan) ----------------
__global__ void zero_cnt_kernel() {
    int i = blockIdx.x * blockDim.x + threadIdx.x;
    if (i < NN) g_cnt[i] = 0;
}

__global__ void count_kernel(const int* __restrict__ dst) {
    int e = blockIdx.x * blockDim.x + threadIdx.x;
    if (e < EE) atomicAdd(&g_cnt[dst[e]], 1);
}

__global__ void partial_sum_kernel() {
    __shared__ int s[256];
    int tid = threadIdx.x;
    s[tid] = g_cnt[blockIdx.x * 256 + tid];
    __syncthreads();
    #pragma unroll
    for (int d = 128; d > 0; d >>= 1) {
        if (tid < d) s[tid] += s[tid + d];
        __syncthreads();
    }
    if (tid == 0) g_blksum[blockIdx.x] = s[0];
}

__global__ void scan512_kernel() {
    __shared__ int s[512];
    int tid = threadIdx.x;
    int v = g_blksum[tid];
    s[tid] = v;
    __syncthreads();
    #pragma unroll
    for (int d = 1; d < 512; d <<= 1) {
        int t = (tid >= d) ? s[tid - d] : 0;
        __syncthreads();
        s[tid] += t;
        __syncthreads();
    }
    g_blkpre[tid] = s[tid] - v;
}

__global__ void writeptr_kernel() {
    __shared__ int s[256];
    int tid = threadIdx.x;
    int i = blockIdx.x * 256 + tid;
    int v = g_cnt[i];
    s[tid] = v;
    __syncthreads();
    #pragma unroll
    for (int d = 1; d < 256; d <<= 1) {
        int t = (tid >= d) ? s[tid - d] : 0;
        __syncthreads();
        s[tid] += t;
        __syncthreads();
    }
    int pos = g_blkpre[blockIdx.x] + s[tid] - v;
    g_rowptr[i] = pos;
    g_cur[i] = pos;
    if (i == NN - 1) g_rowptr[NN] = EE;
}

__global__ void fill_kernel(const int* __restrict__ src, const int* __restrict__ dst,
                            const int* __restrict__ etype,
                            const float* __restrict__ mask, const float* __restrict__ mask2) {
    int e = blockIdx.x * blockDim.x + threadIdx.x;
    if (e >= EE) return;
    int d = dst[e];
    int pos = atomicAdd(&g_cur[d], 1);
    g_se[pos] = src[e] * DD + etype[e];
    g_n1[pos] = mask[e];
    g_n2[pos] = mask2[e];
}

// ---------------- basis gather: AGGB[node] = sum_e w*C[et,b]*h[src], b=0,1 ----------------
// 16 threads per node (float4 lanes)
__global__ void gather2_kernel(const float* __restrict__ h, const float* __restrict__ norm,
                               const float* __restrict__ C6, int nNodes) {
    int t = blockIdx.x * blockDim.x + threadIdx.x;
    int node = t >> 4;
    int lane = t & 15;
    if (node >= nNodes) return;
    float c00 = __ldg(C6 + 0), c01 = __ldg(C6 + 1);
    float c10 = __ldg(C6 + 2), c11 = __ldg(C6 + 3);
    float c20 = __ldg(C6 + 4), c21 = __ldg(C6 + 5);
    int e0 = g_rowptr[node];
    int e1 = g_rowptr[node + 1];
    float4 a0 = make_float4(0.f, 0.f, 0.f, 0.f);
    float4 a1 = make_float4(0.f, 0.f, 0.f, 0.f);
    int e = e0;
    #pragma unroll 1
    for (; e + 2 <= e1; e += 2) {
        int   pA = __ldg(&g_se[e]),      pB = __ldg(&g_se[e + 1]);
        float wA = __ldg(&norm[e]),      wB = __ldg(&norm[e + 1]);
        int  etA = pA & 63,              etB = pB & 63;
        const float4* vA = (const float4*)(h + (pA & ~63) + lane * 4);
        const float4* vB = (const float4*)(h + (pB & ~63) + lane * 4);
        float4 hA = *vA, hB = *vB;
        float wA0 = wA * (etA == 0 ? c00 : (etA == 1 ? c10 : c20));
        float wA1 = wA * (etA == 0 ? c01 : (etA == 1 ? c11 : c21));
        float wB0 = wB * (etB == 0 ? c00 : (etB == 1 ? c10 : c20));
        float wB1 = wB * (etB == 0 ? c01 : (etB == 1 ? c11 : c21));
        a0.x = fmaf(wA0, hA.x, a0.x); a0.y = fmaf(wA0, hA.y, a0.y);
        a0.z = fmaf(wA0, hA.z, a0.z); a0.w = fmaf(wA0, hA.w, a0.w);
        a1.x = fmaf(wA1, hA.x, a1.x); a1.y = fmaf(wA1, hA.y, a1.y);
        a1.z = fmaf(wA1, hA.z, a1.z); a1.w = fmaf(wA1, hA.w, a1.w);
        a0.x = fmaf(wB0, hB.x, a0.x); a0.y = fmaf(wB0, hB.y, a0.y);
        a0.z = fmaf(wB0, hB.z, a0.z); a0.w = fmaf(wB0, hB.w, a0.w);
        a1.x = fmaf(wB1, hB.x, a1.x); a1.y = fmaf(wB1, hB.y, a1.y);
        a1.z = fmaf(wB1, hB.z, a1.z); a1.w = fmaf(wB1, hB.w, a1.w);
    }
    if (e < e1) {
        int   p = __ldg(&g_se[e]);
        float w = __ldg(&norm[e]);
        int  et = p & 63;
        float4 hv = *(const float4*)(h + (p & ~63) + lane * 4);
        float w0 = w * (et == 0 ? c00 : (et == 1 ? c10 : c20));
        float w1 = w * (et == 0 ? c01 : (et == 1 ? c11 : c21));
        a0.x = fmaf(w0, hv.x, a0.x); a0.y = fmaf(w0, hv.y, a0.y);
        a0.z = fmaf(w0, hv.z, a0.z); a0.w = fmaf(w0, hv.w, a0.w);
        a1.x = fmaf(w1, hv.x, a1.x); a1.y = fmaf(w1, hv.y, a1.y);
        a1.z = fmaf(w1, hv.z, a1.z); a1.w = fmaf(w1, hv.w, a1.w);
    }
    *(float4*)(g_AGGB + (size_t)node * 128 + lane * 4)      = a0;
    *(float4*)(g_AGGB + (size_t)node * 128 + 64 + lane * 4) = a1;
}

// ---------------- stage-2 GEMM: H = act( [AGGB | h] @ Wk + bias ) ----------------
// tile 128 rows x 64 cols, K=192 in 3 chunks of 64; 8 warps, each 16 rows x 64 cols
__device__ __forceinline__ unsigned f2tf32(float x) {
    unsigned r;
    asm("cvt.rna.tf32.f32 %0, %1;" : "=r"(r) : "f"(x));
    return r;
}

__device__ __forceinline__ void mma_tf32(float* c, const unsigned* a, const unsigned* b) {
    asm volatile(
        "mma.sync.aligned.m16n8k8.row.col.f32.tf32.tf32.f32 "
        "{%0,%1,%2,%3}, {%4,%5,%6,%7}, {%8,%9}, {%0,%1,%2,%3};"
        : "+f"(c[0]), "+f"(c[1]), "+f"(c[2]), "+f"(c[3])
        : "r"(a[0]), "r"(a[1]), "r"(a[2]), "r"(a[3]), "r"(b[0]), "r"(b[1]));
}

#define XS 68
#define WS2 72

template <int ACT>   // 0 = ELU, 1 = leaky_relu(0.01)
__global__ __launch_bounds__(256, 2)
void gemm2_kernel(const float* __restrict__ h, int conv, float* __restrict__ Hout) {
    extern __shared__ float smem[];
    float* As = smem;                  // [128][68]
    float* Ws = smem + 128 * XS;       // [64][72]

    const float* Wp = g_Wk + (size_t)conv * 192 * DD;
    int tid = threadIdx.x;
    int row0 = blockIdx.x * 128;
    int warp = tid >> 5;
    int lane = tid & 31;
    int group = lane >> 2;
    int q     = lane & 3;

    float acc[8][4];
    #pragma unroll
    for (int ni = 0; ni < 8; ni++)
        #pragma unroll
        for (int t = 0; t < 4; t++) acc[ni][t] = 0.f;

    #pragma unroll
    for (int chunk = 0; chunk < 3; chunk++) {
        // load X chunk (128x64)
        #pragma unroll
        for (int it = 0; it < 8; it++) {
            int f = tid + it * 256;
            int row = f >> 4, k4 = f & 15;
            float4 v;
            if (chunk < 2)
                v = *(const float4*)(g_AGGB + (size_t)(row0 + row) * 128 + chunk * 64 + k4 * 4);
            else
                v = *(const float4*)(h + (size_t)(row0 + row) * DD + k4 * 4);
            *(float4*)(As + row * XS + k4 * 4) = v;
        }
        // load W chunk (64x64)
        #pragma unroll
        for (int it = 0; it < 4; it++) {
            int f = tid + it * 256;
            int k = f >> 4, c4 = f & 15;
            *(float4*)(Ws + k * WS2 + c4 * 4) =
                *(const float4*)(Wp + (size_t)(chunk * 64 + k) * DD + c4 * 4);
        }
        __syncthreads();

        #pragma unroll
        for (int ks = 0; ks < 8; ks++) {
            int k0 = ks * 8;
            int rb = warp * 16 + group;
            float a0 = As[rb * XS + k0 + q];
            float a1 = As[(rb + 8) * XS + k0 + q];
            float a2 = As[rb * XS + k0 + q + 4];
            float a3 = As[(rb + 8) * XS + k0 + q + 4];
            unsigned abig[4], ares[4];
            abig[0] = f2tf32(a0); ares[0] = f2tf32(a0 - __uint_as_float(abig[0]));
            abig[1] = f2tf32(a1); ares[1] = f2tf32(a1 - __uint_as_float(abig[1]));
            abig[2] = f2tf32(a2); ares[2] = f2tf32(a2 - __uint_as_float(abig[2]));
            abig[3] = f2tf32(a3); ares[3] = f2tf32(a3 - __uint_as_float(abig[3]));
            #pragma unroll
            for (int ni = 0; ni < 8; ni++) {
                int cn = ni * 8 + group;
                float b0f = Ws[(k0 + q) * WS2 + cn];
                float b1f = Ws[(k0 + q + 4) * WS2 + cn];
                unsigned bbig[2], bres[2];
                bbig[0] = f2tf32(b0f); bres[0] = f2tf32(b0f - __uint_as_float(bbig[0]));
                bbig[1] = f2tf32(b1f); bres[1] = f2tf32(b1f - __uint_as_float(bbig[1]));
                mma_tf32(acc[ni], ares, bbig);
                mma_tf32(acc[ni], abig, bres);
                mma_tf32(acc[ni], abig, bbig);
            }
        }
        __syncthreads();
    }

    // epilogue: +bias, activation, write
    #pragma unroll
    for (int ni = 0; ni < 8; ni++) {
        int cg = ni * 8 + 2 * q;
        float bv0 = g_Bpack[conv * DD + cg];
        float bv1 = g_Bpack[conv * DD + cg + 1];
        float v0 = acc[ni][0] + bv0, v1 = acc[ni][1] + bv1;
        float v2 = acc[ni][2] + bv0, v3 = acc[ni][3] + bv1;
        if (ACT == 0) {
            v0 = v0 > 0.f ? v0 : expm1f(v0);
            v1 = v1 > 0.f ? v1 : expm1f(v1);
            v2 = v2 > 0.f ? v2 : expm1f(v2);
            v3 = v3 > 0.f ? v3 : expm1f(v3);
        } else {
            v0 = v0 >= 0.f ? v0 : 0.01f * v0;
            v1 = v1 >= 0.f ? v1 : 0.01f * v1;
            v2 = v2 >= 0.f ? v2 : 0.01f * v2;
            v3 = v3 >= 0.f ? v3 : 0.01f * v3;
        }
        int r0 = row0 + warp * 16 + group;
        *(float2*)(Hout + (size_t)r0 * DD + cg)       = make_float2(v0, v1);
        *(float2*)(Hout + (size_t)(r0 + 8) * DD + cg) = make_float2(v2, v3);
    }
}

// ---------------- MLP head ----------------
__global__ void mlp_kernel(const float* __restrict__ w1, const float* __restrict__ b1,
                           const float* __restrict__ w2, const float* __restrict__ b2,
                           float* __restrict__ out) {
    __shared__ float sub[192];
    __shared__ float red[128];
    int n = blockIdx.x;
    int tid = threadIdx.x;
    if (tid < 64) {
        sub[tid]       = g_Hg0[(size_t)n * DD + tid];
        sub[64 + tid]  = g_Hg1[(size_t)n * DD + tid];
        sub[128 + tid] = g_Hg2[(size_t)n * DD + tid];
    }
    __syncthreads();
    float acc = b1[tid];
    const float* w1r = w1 + tid * 192;
    #pragma unroll 8
    for (int k = 0; k < 192; k++) acc += sub[k] * w1r[k];
    red[tid] = fmaxf(acc, 0.f) * w2[tid];
    __syncthreads();
    #pragma unroll
    for (int s = 64; s > 0; s >>= 1) {
        if (tid < s) red[tid] += red[tid + s];
        __syncthreads();
    }
    if (tid == 0) {
        float z = red[0] + b2[0];
        out[n] = 1.f / (1.f + expf(-z));
    }
}

// ---------------- launch ----------------
extern "C" void kernel_launch(void* const* d_in, const int* in_sizes, int n_in,
                              void* d_out, int out_size) {
    const float* x     = (const float*)d_in[0];
    const int*   src   = (const int*)d_in[1];
    const int*   dst   = (const int*)d_in[2];
    const int*   etype = (const int*)d_in[3];
    const float* mask  = (const float*)d_in[4];
    const float* mask2 = (const float*)d_in[5];
    const float* lV = (const float*)d_in[6];
    const float* lC = (const float*)d_in[7];
    const float* lW = (const float*)d_in[8];
    const float* lB = (const float*)d_in[9];
    const float* gV = (const float*)d_in[10];
    const float* gC = (const float*)d_in[11];
    const float* gW = (const float*)d_in[12];
    const float* gB = (const float*)d_in[13];
    const float* w1 = (const float*)d_in[14];
    const float* b1 = (const float*)d_in[15];
    const float* w2 = (const float*)d_in[16];
    const float* b2 = (const float*)d_in[17];
    float* out = (float*)d_out;

    float *Hl, *Hg0, *Hg1, *Hg2, *n1p, *n2p;
    cudaGetSymbolAddress((void**)&Hl,  g_Hl);
    cudaGetSymbolAddress((void**)&Hg0, g_Hg0);
    cudaGetSymbolAddress((void**)&Hg1, g_Hg1);
    cudaGetSymbolAddress((void**)&Hg2, g_Hg2);
    cudaGetSymbolAddress((void**)&n1p, g_n1);
    cudaGetSymbolAddress((void**)&n2p, g_n2);

    const int GEMM_SMEM = (128 * XS + 64 * WS2) * 4;
    cudaFuncSetAttribute(gemm2_kernel<0>, cudaFuncAttributeMaxDynamicSharedMemorySize, GEMM_SMEM);
    cudaFuncSetAttribute(gemm2_kernel<1>, cudaFuncAttributeMaxDynamicSharedMemorySize, GEMM_SMEM);

    prep_weights<<<(6 * 192 * DD + 255) / 256, 256>>>(lV, lW, lB, gV, gW, gB);
    zero_cnt_kernel<<<NN / 256, 256>>>();
    count_kernel<<<EE / 256, 256>>>(dst);
    partial_sum_kernel<<<512, 256>>>();
    scan512_kernel<<<1, 512>>>();
    writeptr_kernel<<<512, 256>>>();
    fill_kernel<<<EE / 256, 256>>>(src, dst, etype, mask, mask2);

    float* hg[3] = {Hg0, Hg1, Hg2};
    const float* h_in = x;
    for (int layer = 0; layer < LL; layer++) {
        // local conv: norm = mask, coeffs lC[layer], ELU
        gather2_kernel<<<(NN * 16) / 256, 256>>>(h_in, n1p, lC + layer * RR * NBASE, NN);
        gemm2_kernel<0><<<NN / 128, 256, GEMM_SMEM>>>(h_in, 2 * layer, Hl);
        // global conv: norm = mask2, coeffs gC[layer], leaky relu; last layer only BB nodes
        int nOut = (layer == LL - 1) ? BB : NN;
        gather2_kernel<<<(nOut * 16 + 255) / 256, 256>>>(Hl, n2p, gC + layer * RR * NBASE, nOut);
        gemm2_kernel<1><<<nOut / 128, 256, GEMM_SMEM>>>(Hl, 2 * layer + 1, hg[layer]);
        h_in = hg[layer];
    }

    mlp_kernel<<<BB, 128>>>(w1, b1, w2, b2, out);
}